// round 4
// baseline (speedup 1.0000x reference)
#include <cuda_runtime.h>
#include <math.h>

#define NTOT   160000   // B*N flattened nodes
#define NNODE  5000
#define NEDGE  80000
#define TSTEPS 12
#define BATCH  32
#define HD     128
#define HORZ   12
#define INF    2

// ---------------- static device scratch (no allocation allowed) ----------------
__device__ float g_h   [NTOT * HD];        // hidden state
__device__ float g_hc  [NTOT * HD];        // cheb_conv(h)
__device__ float g_zr  [NTOT * 2 * HD];    // [z | r] gates
__device__ float g_f   [NTOT * 6];         // rank-6 ic features per node
__device__ float g_P1  [NNODE * HD];       // prop(h)
__device__ float g_P2  [NNODE * HD];       // prop(prop(h))
__device__ float g_X1  [NNODE * INF];      // prop(x_t)
__device__ float g_X2  [NNODE * INF];      // prop(prop(x_t))
__device__ float g_norm[NEDGE];
__device__ int   g_degsrc[NNODE];
__device__ int   g_cnt [NNODE];
__device__ int   g_off [NNODE + 1];
__device__ int   g_cur [NNODE];
__device__ int   g_csrsrc[NEDGE];
__device__ float g_csrw  [NEDGE];
__device__ float g_A2eff [HD * HD];        // W2[0]-W2[2]
__device__ float g_Wzrb  [HD * 2 * HD];    // bottom rows of [Wz|Wr] : [128,256]
__device__ float g_M6zr  [6 * 2 * HD];     // rank-6 ic -> zr gates
__device__ float g_biaszr[2 * HD];
__device__ float g_M6c   [6 * HD];         // rank-6 ic -> candidate
__device__ float g_biasc [HD];
__device__ int   g_bad64;                  // edge dtype probe
__device__ int   g_is64;

// ---------------- edge_index dtype handling ----------------
// The harness may deliver int64 edge_index as int32. Probe: valid-as-int64
// requires EVERY 8-byte word in [0, NNODE) — impossible for packed int32 pairs.
__global__ void detect_dtype_kernel(const void* __restrict__ ei) {
    int e = blockIdx.x * blockDim.x + threadIdx.x;
    if (e >= 2 * NEDGE) return;
    long long v = ((const long long*)ei)[e];
    if (v < 0 || v >= NNODE) atomicOr(&g_bad64, 1);
}
__global__ void set_is64_kernel() { g_is64 = g_bad64 ? 0 : 1; }

__device__ __forceinline__ int edge_at(const void* __restrict__ ei, int idx) {
    int s;
    if (g_is64) s = (int)((const long long*)ei)[idx];
    else        s = ((const int*)ei)[idx];
    // clamp: never fault, even under a wrong dtype theory
    if (s < 0) s = 0;
    if (s >= NNODE) s = NNODE - 1;
    return s;
}

// ---------------- tiny setup kernels ----------------
__global__ void zero_h_kernel() {
    int i = blockIdx.x * blockDim.x + threadIdx.x;
    if (i < NTOT * HD) g_h[i] = 0.f;
}

__global__ void zero_counts_kernel() {
    int i = blockIdx.x * blockDim.x + threadIdx.x;
    if (i < NNODE) g_degsrc[i] = 0;
    else if (i < 2 * NNODE) g_cnt[i - NNODE] = 0;
    if (i == 0) g_bad64 = 0;
}

__global__ void count_edges_kernel(const void* __restrict__ ei) {
    int e = blockIdx.x * blockDim.x + threadIdx.x;
    if (e >= NEDGE) return;
    int s = edge_at(ei, e);
    int d = edge_at(ei, NEDGE + e);
    atomicAdd(&g_degsrc[s], 1);
    atomicAdd(&g_cnt[d], 1);
}

__global__ void norm_kernel(const void* __restrict__ ei) {
    int e = blockIdx.x * blockDim.x + threadIdx.x;
    if (e >= NEDGE) return;
    int s = edge_at(ei, e);
    int d = edge_at(ei, NEDGE + e);
    int ds = g_degsrc[s], dd = g_degsrc[d];
    float is = (ds > 0) ? rsqrtf((float)ds) : 0.f;
    float id = (dd > 0) ? rsqrtf((float)dd) : 0.f;
    g_norm[e] = -is * id;
}

__global__ void scan_kernel() {   // exclusive scan of g_cnt -> g_off/g_cur (1 block, 1024 thr)
    __shared__ int sh[1024];
    int t = threadIdx.x;
    int start = t * 5;
    int end = start + 5; if (end > NNODE) end = NNODE;
    int s = 0;
    for (int i = start; i < end && i < NNODE; i++) s += g_cnt[i];
    sh[t] = s;
    __syncthreads();
    for (int off = 1; off < 1024; off <<= 1) {
        int v = (t >= off) ? sh[t - off] : 0;
        __syncthreads();
        sh[t] += v;
        __syncthreads();
    }
    int run = (t == 0) ? 0 : sh[t - 1];
    for (int i = start; i < end && i < NNODE; i++) {
        g_off[i] = run; g_cur[i] = run; run += g_cnt[i];
    }
    if (t == 1023) g_off[NNODE] = sh[1023];
}

__global__ void fill_kernel(const void* __restrict__ ei) {
    int e = blockIdx.x * blockDim.x + threadIdx.x;
    if (e >= NEDGE) return;
    int s = edge_at(ei, e);
    int d = edge_at(ei, NEDGE + e);
    int p = atomicAdd(&g_cur[d], 1);
    if (p >= NEDGE) p = NEDGE - 1;   // defensive
    g_csrsrc[p] = s;
    g_csrw[p]   = g_norm[e];
}

__global__ void build_A2eff_kernel(const float* __restrict__ W2) {
    int i = blockIdx.x * blockDim.x + threadIdx.x;
    if (i < HD * HD) g_A2eff[i] = W2[i] - W2[2 * HD * HD + i];
}

__global__ void build_Wzrb_kernel(const float* __restrict__ Wz, const float* __restrict__ Wr) {
    int i = blockIdx.x * blockDim.x + threadIdx.x;
    if (i >= HD * 2 * HD) return;
    int k = i >> 8;          // / 256
    int j = i & 255;
    g_Wzrb[i] = (j < HD) ? Wz[(HD + k) * HD + j] : Wr[(HD + k) * HD + (j - HD)];
}

// rank-6 ic folding rows: (A1eff c0, A1eff c1, W1[1] c0, W1[1] c1, 2*W1[2] c0, 2*W1[2] c1)
__device__ __forceinline__ float ic_row_elem(const float* W1, const float* b1, int r, int k) {
    switch (r) {
        case 0: return W1[k]        - W1[512 + k];
        case 1: return W1[128 + k]  - W1[640 + k];
        case 2: return W1[256 + k];
        case 3: return W1[384 + k];
        case 4: return 2.f * W1[512 + k];
        case 5: return 2.f * W1[640 + k];
        default: return b1[k];
    }
}

__global__ void build_zr_fold_kernel(const float* __restrict__ W1, const float* __restrict__ b1,
                                     const float* __restrict__ Wz, const float* __restrict__ bz,
                                     const float* __restrict__ Wr, const float* __restrict__ br) {
    int idx = blockIdx.x * blockDim.x + threadIdx.x;
    if (idx >= 7 * 256) return;
    int r = idx / 256, j = idx % 256;
    const float* Wtop = (j < HD) ? Wz : Wr;
    int jj = j & (HD - 1);
    float s = 0.f;
    for (int k = 0; k < HD; k++) s += ic_row_elem(W1, b1, r, k) * Wtop[k * HD + jj];
    if (r < 6) g_M6zr[r * 256 + j] = s;
    else       g_biaszr[j] = s + ((j < HD) ? bz[jj] : br[jj]);
}

__global__ void build_c_fold_kernel(const float* __restrict__ W1, const float* __restrict__ b1,
                                    const float* __restrict__ Wc, const float* __restrict__ bc) {
    int idx = blockIdx.x * blockDim.x + threadIdx.x;
    if (idx >= 7 * HD) return;
    int r = idx / HD, j = idx % HD;
    float s = 0.f;
    for (int k = 0; k < HD; k++) s += ic_row_elem(W1, b1, r, k) * Wc[k * HD + j];
    if (r < 6) g_M6c[r * HD + j] = s;
    else       g_biasc[j] = s + bc[j];
}

// ---------------- graph propagation (CSR gather) ----------------
__global__ void prop128_kernel(int sel) {  // sel 0: h->P1, sel 1: P1->P2
    const float* tin  = sel ? g_P1 : g_h;
    float*       tout = sel ? g_P2 : g_P1;
    int d = blockIdx.x, j = threadIdx.x;
    int p0 = g_off[d], p1 = g_off[d + 1];
    float acc = 0.f;
    for (int p = p0; p < p1; p++)
        acc = fmaf(g_csrw[p], tin[g_csrsrc[p] * HD + j], acc);
    tout[d * HD + j] = acc;
}

__global__ void prop2_kernel(const float* __restrict__ xin, int sel) { // sel 0: x_t->X1, 1: X1->X2
    int idx = blockIdx.x * blockDim.x + threadIdx.x;
    if (idx >= NNODE * INF) return;
    int d = idx >> 1, c = idx & 1;
    const float* tin  = sel ? g_X1 : xin;
    float*       tout = sel ? g_X2 : g_X1;
    int p0 = g_off[d], p1 = g_off[d + 1];
    float acc = 0.f;
    for (int p = p0; p < p1; p++)
        acc = fmaf(g_csrw[p], tin[g_csrsrc[p] * INF + c], acc);
    tout[idx] = acc;
}

__global__ void build_f_kernel(const float* __restrict__ x, int t) {
    int i = blockIdx.x * blockDim.x + threadIdx.x;
    if (i >= NTOT) return;
    int b = i / NNODE, n = i - b * NNODE;
    const float* xr = x + ((size_t)(b * TSTEPS + t) * NNODE + n) * INF;
    float* f = g_f + (size_t)i * 6;
    f[0] = xr[0]; f[1] = xr[1];
    if (i < NNODE) {
        f[2] = g_X1[i * 2];     f[3] = g_X1[i * 2 + 1];
        f[4] = g_X2[i * 2];     f[5] = g_X2[i * 2 + 1];
    } else {
        f[2] = 0.f; f[3] = 0.f; f[4] = 0.f; f[5] = 0.f;
    }
}

// ---------------- fused SGEMM ----------------
// MODE 0: g_hc = A@B + bias          (hc main)
// MODE 3: g_hc += A@B                (5000-row cheb correction; A=[P1|2*P2], K=256)
// MODE 1: g_zr = sigmoid(A@B + f@M6zr + biaszr)          (A=hc)
// MODE 2: g_h  = z*h + (1-z)*tanh(A@B + f@M6c + biasc)   (A=r.*hc, USE_R)
#define GBM 128
#define GBN 64
#define GBK 16

template <int MODE, bool USE_A2, bool USE_R>
__global__ __launch_bounds__(256)
void gemm_kernel(int aSel, const float* __restrict__ Bext, const float* __restrict__ biasExt,
                 int M, int Ncols, int Ktot, float a2scale) {
    const float* A1;
    const float* A2 = nullptr;
    if (aSel == 0)      A1 = g_h;
    else if (aSel == 1) A1 = g_hc;
    else              { A1 = g_P1; A2 = g_P2; }
    const float* B = Bext ? Bext : (MODE == 0 ? g_A2eff : g_Wzrb);

    __shared__ float As[GBK][GBM];
    __shared__ float Bs[GBK][GBN];

    int tid  = threadIdx.x;
    int row0 = blockIdx.y * GBM;
    int col0 = blockIdx.x * GBN;

    float acc[8][4];
#pragma unroll
    for (int i = 0; i < 8; i++)
#pragma unroll
        for (int j = 0; j < 4; j++) acc[i][j] = 0.f;

    int arow = tid >> 1;
    int ak   = (tid & 1) << 3;   // 0 or 8
    int bk   = tid >> 4;
    int bj   = (tid & 15) << 2;
    int ty   = tid >> 4;
    int tx   = tid & 15;

    for (int kt = 0; kt < Ktot; kt += GBK) {
        int gr = row0 + arow;
#pragma unroll
        for (int q = 0; q < 2; q++) {
            int gk = kt + ak + q * 4;
            float4 av = make_float4(0.f, 0.f, 0.f, 0.f);
            if (gr < M) {
                if (!USE_A2 || gk < 128) {
                    av = *reinterpret_cast<const float4*>(A1 + (size_t)gr * 128 + gk);
                    if (USE_R) {
                        float4 rv = *reinterpret_cast<const float4*>(g_zr + (size_t)gr * 256 + 128 + gk);
                        av.x *= rv.x; av.y *= rv.y; av.z *= rv.z; av.w *= rv.w;
                    }
                } else {
                    av = *reinterpret_cast<const float4*>(A2 + (size_t)gr * 128 + (gk - 128));
                    av.x *= a2scale; av.y *= a2scale; av.z *= a2scale; av.w *= a2scale;
                }
            }
            As[ak + q * 4 + 0][arow] = av.x;
            As[ak + q * 4 + 1][arow] = av.y;
            As[ak + q * 4 + 2][arow] = av.z;
            As[ak + q * 4 + 3][arow] = av.w;
        }
        float4 bv = *reinterpret_cast<const float4*>(B + (size_t)(kt + bk) * Ncols + col0 + bj);
        *reinterpret_cast<float4*>(&Bs[bk][bj]) = bv;
        __syncthreads();
#pragma unroll
        for (int k = 0; k < GBK; k++) {
            float4 rb = *reinterpret_cast<const float4*>(&Bs[k][tx << 2]);
#pragma unroll
            for (int i = 0; i < 8; i++) {
                float ra = As[k][(ty << 3) + i];
                acc[i][0] = fmaf(ra, rb.x, acc[i][0]);
                acc[i][1] = fmaf(ra, rb.y, acc[i][1]);
                acc[i][2] = fmaf(ra, rb.z, acc[i][2]);
                acc[i][3] = fmaf(ra, rb.w, acc[i][3]);
            }
        }
        __syncthreads();
    }

#pragma unroll
    for (int i = 0; i < 8; i++) {
        int gr = row0 + (ty << 3) + i;
        if (gr >= M) break;
        float fv0 = 0, fv1 = 0, fv2 = 0, fv3 = 0, fv4 = 0, fv5 = 0;
        if (MODE == 1 || MODE == 2) {
            const float* f = g_f + (size_t)gr * 6;
            fv0 = f[0]; fv1 = f[1]; fv2 = f[2]; fv3 = f[3]; fv4 = f[4]; fv5 = f[5];
        }
#pragma unroll
        for (int j = 0; j < 4; j++) {
            int gc = col0 + (tx << 2) + j;
            float v = acc[i][j];
            if (MODE == 0) {
                g_hc[(size_t)gr * 128 + gc] = v + biasExt[gc];
            } else if (MODE == 3) {
                g_hc[(size_t)gr * 128 + gc] += v;
            } else if (MODE == 1) {
                v += g_biaszr[gc]
                   + fv0 * g_M6zr[gc]        + fv1 * g_M6zr[256 + gc]
                   + fv2 * g_M6zr[512 + gc]  + fv3 * g_M6zr[768 + gc]
                   + fv4 * g_M6zr[1024 + gc] + fv5 * g_M6zr[1280 + gc];
                g_zr[(size_t)gr * 256 + gc] = 1.f / (1.f + expf(-v));
            } else {  // MODE 2 : fused GRU update, in-place h
                v += g_biasc[gc]
                   + fv0 * g_M6c[gc]       + fv1 * g_M6c[128 + gc]
                   + fv2 * g_M6c[256 + gc] + fv3 * g_M6c[384 + gc]
                   + fv4 * g_M6c[512 + gc] + fv5 * g_M6c[640 + gc];
                float z  = g_zr[(size_t)gr * 256 + gc];
                float hp = g_h[(size_t)gr * 128 + gc];
                g_h[(size_t)gr * 128 + gc] = z * hp + (1.f - z) * tanhf(v);
            }
        }
    }
}

// ---------------- output head ----------------
__global__ void out_kernel(const float* __restrict__ Wo, const float* __restrict__ bo,
                           float* __restrict__ out) {
    int idx = blockIdx.x * blockDim.x + threadIdx.x;
    if (idx >= NTOT * HORZ) return;
    int i = idx / HORZ, hor = idx - i * HORZ;
    const float* hr = g_h + (size_t)i * HD;
    float s = bo[hor];
#pragma unroll 8
    for (int k = 0; k < HD; k++) s = fmaf(hr[k], Wo[k * HORZ + hor], s);
    int b = i / NNODE, n = i - b * NNODE;
    out[(size_t)(b * HORZ + hor) * NNODE + n] = s;
}

// ---------------- launch ----------------
extern "C" void kernel_launch(void* const* d_in, const int* in_sizes, int n_in,
                              void* d_out, int out_size) {
    const float* x  = (const float*)d_in[0];
    const void*  ei = d_in[1];                  // int32 or int64, auto-detected on device
    const float* W1 = (const float*)d_in[2];
    const float* b1 = (const float*)d_in[3];
    const float* W2 = (const float*)d_in[4];
    const float* b2 = (const float*)d_in[5];
    const float* Wz = (const float*)d_in[6];
    const float* bz = (const float*)d_in[7];
    const float* Wr = (const float*)d_in[8];
    const float* br = (const float*)d_in[9];
    const float* Wc = (const float*)d_in[10];
    const float* bc = (const float*)d_in[11];
    const float* Wo = (const float*)d_in[12];
    const float* bo = (const float*)d_in[13];
    float* out = (float*)d_out;
    (void)in_sizes; (void)n_in; (void)out_size;

    // setup
    zero_h_kernel<<<(NTOT * HD + 1023) / 1024, 1024>>>();
    zero_counts_kernel<<<(2 * NNODE + 255) / 256, 256>>>();
    detect_dtype_kernel<<<(2 * NEDGE + 255) / 256, 256>>>(ei);
    set_is64_kernel<<<1, 1>>>();
    count_edges_kernel<<<(NEDGE + 255) / 256, 256>>>(ei);
    norm_kernel<<<(NEDGE + 255) / 256, 256>>>(ei);
    scan_kernel<<<1, 1024>>>();
    fill_kernel<<<(NEDGE + 255) / 256, 256>>>(ei);
    build_A2eff_kernel<<<(HD * HD + 255) / 256, 256>>>(W2);
    build_Wzrb_kernel<<<(HD * 2 * HD + 255) / 256, 256>>>(Wz, Wr);
    build_zr_fold_kernel<<<(7 * 256 + 255) / 256, 256>>>(W1, b1, Wz, bz, Wr, br);
    build_c_fold_kernel<<<(7 * HD + 255) / 256, 256>>>(W1, b1, Wc, bc);

    for (int t = 0; t < TSTEPS; t++) {
        const float* xt0 = x + (size_t)t * NNODE * INF;   // batch 0, timestep t
        prop2_kernel<<<(NNODE * INF + 127) / 128, 128>>>(xt0, 0);
        prop2_kernel<<<(NNODE * INF + 127) / 128, 128>>>(xt0, 1);
        prop128_kernel<<<NNODE, HD>>>(0);
        prop128_kernel<<<NNODE, HD>>>(1);
        build_f_kernel<<<(NTOT + 255) / 256, 256>>>(x, t);

        // hc = h @ (W2[0]-W2[2]) + b2
        gemm_kernel<0, false, false><<<dim3(2, (NTOT + GBM - 1) / GBM), 256>>>(
            0, nullptr, b2, NTOT, 128, 128, 1.f);
        // hc[0:5000] += P1@W2[1] + 2*P2@W2[2]
        gemm_kernel<3, true, false><<<dim3(2, (NNODE + GBM - 1) / GBM), 256>>>(
            2, W2 + HD * HD, nullptr, NNODE, 128, 256, 2.f);
        // zr = sigmoid(hc @ Wzr_bot + f@M6zr + biaszr)
        gemm_kernel<1, false, false><<<dim3(4, (NTOT + GBM - 1) / GBM), 256>>>(
            1, nullptr, nullptr, NTOT, 256, 128, 1.f);
        // h = z*h + (1-z)*tanh((r.*hc) @ Wc_bot + f@M6c + biasc)
        gemm_kernel<2, false, true><<<dim3(2, (NTOT + GBM - 1) / GBM), 256>>>(
            1, Wc + HD * HD, nullptr, NTOT, 128, 128, 1.f);
    }

    out_kernel<<<(NTOT * HORZ + 255) / 256, 256>>>(Wo, bo, out);
}